// round 5
// baseline (speedup 1.0000x reference)
#include <cuda_runtime.h>

#define Bn 4
#define Cn 256
#define Nn 131072          // D*H*W
#define NVEC (Nn / 4)      // 32768 float4 per batch
#define Kk 256
#define FCAP 5632          // shared candidate capacity (expected ~2.9K)

// ---------------- device scratch (static globals; no allocation) ------------
__device__ float4   g_scores4[Bn * NVEC];   // 2 MiB scores
__device__ unsigned g_hist[Bn * 256];       // MSB-byte histograms (self-reset)
__device__ int      g_topk[Bn * Kk];

// monotone float->uint key: larger float => larger key
__device__ __forceinline__ unsigned fkey(float f) {
    unsigned u = __float_as_uint(f);
    return (u & 0x80000000u) ? ~u : (u | 0x80000000u);
}

// Warp-parallel straddling-bin selection over 32*NPL bins (higher index =
// higher rank). Finds max bin i where count(bins > i) < kk <= count(bins >= i).
template<int NPL>
__device__ __forceinline__ void warp_select(const unsigned* __restrict__ h,
                                            int kk, unsigned* out_idx, int* out_kk) {
    const int lane = threadIdx.x & 31;
    unsigned loc[NPL];
    unsigned chunk = 0;
#pragma unroll
    for (int j = 0; j < NPL; j++) { loc[j] = h[lane * NPL + j]; chunk += loc[j]; }
    unsigned pref = chunk;                       // inclusive prefix low->high lane
#pragma unroll
    for (int o = 1; o < 32; o <<= 1) {
        unsigned v = __shfl_up_sync(0xffffffffu, pref, o);
        if (lane >= o) pref += v;
    }
    unsigned total = __shfl_sync(0xffffffffu, pref, 31);
    unsigned cum = total - pref;                 // entries in higher lanes
#pragma unroll
    for (int j = NPL - 1; j >= 0; j--) {
        unsigned nc = cum + loc[j];
        if (cum < (unsigned)kk && nc >= (unsigned)kk) {
            *out_idx = (unsigned)(lane * NPL + j);
            *out_kk  = kk - (int)cum;
        }
        cum = nc;
    }
}

// ---------------- kernel 1: score + fused MSB histogram ---------------------
__global__ void score_kernel(const float4* __restrict__ F,
                             const float*  __restrict__ w) {
    __shared__ float sw[Cn];
    __shared__ unsigned hist[256];
    for (int i = threadIdx.x; i < Cn; i += blockDim.x) sw[i] = w[i];
    for (int i = threadIdx.x; i < 256; i += blockDim.x) hist[i] = 0;
    __syncthreads();

    int v  = blockIdx.x * blockDim.x + threadIdx.x;   // [0, Bn*NVEC)
    int b  = v >> 15;                                  // / NVEC
    int nv = v & (NVEC - 1);
    const float4* base = F + (size_t)b * Cn * NVEC + nv;

    float ax = 0.f, ay = 0.f, az = 0.f, aw = 0.f;
#pragma unroll 8
    for (int c = 0; c < Cn; c++) {
        float4 x = __ldcs(&base[(size_t)c * NVEC]);   // streaming: no reuse
        float wc = sw[c];
        ax = fmaf(x.x, wc, ax);
        ay = fmaf(x.y, wc, ay);
        az = fmaf(x.z, wc, az);
        aw = fmaf(x.w, wc, aw);
    }
    g_scores4[v] = make_float4(ax, ay, az, aw);

    unsigned kb[4] = { fkey(ax) >> 24, fkey(ay) >> 24, fkey(az) >> 24, fkey(aw) >> 24 };
    const int lane = threadIdx.x & 31;
#pragma unroll
    for (int j = 0; j < 4; j++) {
        unsigned mask = __match_any_sync(0xffffffffu, kb[j]);
        if (lane == (__ffs(mask) - 1))
            atomicAdd(&hist[kb[j]], (unsigned)__popc(mask));
    }
    __syncthreads();
    unsigned* gh = g_hist + b * 256;
    for (int i = threadIdx.x; i < 256; i += blockDim.x)
        if (hist[i]) atomicAdd(&gh[i], hist[i]);
}

// ---------------- kernel 2: fused select (bin pick + compact + radix + topk)
__global__ void __launch_bounds__(1024, 1) selectk_kernel() {
    const int b = blockIdx.x, t = threadIdx.x;        // 1024 threads
    const float4* s4 = g_scores4 + (size_t)b * NVEC;

    __shared__ unsigned skey[FCAP];                   // 22 KB
    __shared__ unsigned sidx[FCAP];                   // 22 KB
    __shared__ unsigned hist[256];
    __shared__ unsigned s_selbin, s_idx2;
    __shared__ int s_kk, s_cgt, s_cnt, s_eq;

    // ---- stage 0: straddling MSB bin from fused histogram, reset state ----
    if (t < 256) {
        hist[t] = g_hist[b * 256 + t];
        g_hist[b * 256 + t] = 0;                      // reset for next replay
    }
    if (t == 0) { s_cgt = 0; s_cnt = 0; s_eq = 0; }
    __syncthreads();
    if (t < 32) warp_select<8>(hist, Kk, &s_selbin, &s_kk);
    __syncthreads();
    const unsigned selbin = s_selbin;
    int kk = s_kk;

    // ---- stage 1: scan scores (L2-resident), direct-write + stash ----
    for (int i = t; i < NVEC; i += 1024) {
        float4 s = s4[i];
        float sv[4] = { s.x, s.y, s.z, s.w };
#pragma unroll
        for (int j = 0; j < 4; j++) {
            unsigned key = fkey(sv[j]);
            unsigned bin = key >> 24;
            if (bin < selbin) continue;
            int n = i * 4 + j;
            if (bin > selbin) {
                int p = atomicAdd(&s_cgt, 1);         // guaranteed < Kk
                g_topk[b * Kk + p] = n;
            } else {
                int p = atomicAdd(&s_cnt, 1);
                if (p < FCAP) { skey[p] = key; sidx[p] = (unsigned)n; }
            }
        }
    }
    __syncthreads();
    const int cnt_raw = s_cnt;
    const int cnt = cnt_raw < FCAP ? cnt_raw : FCAP;
    const bool fb = (cnt_raw > FCAP);                 // fallback: rescan scores

    // ---- stage 2: 3 radix levels (8-bit) in shared ----
    unsigned prefix = selbin << 24, pmask = 0xFF000000u;
    for (int level = 2; level >= 0; level--) {
        if (t < 256) hist[t] = 0;
        __syncthreads();
        const int sh = 8 * level;
        if (!fb) {
            for (int i = t; i < cnt; i += 1024) {
                unsigned key = skey[i];
                if ((key & pmask) == prefix)
                    atomicAdd(&hist[(key >> sh) & 255], 1u);
            }
        } else {
            const float* sc = (const float*)s4;
            for (int i = t; i < Nn; i += 1024) {
                unsigned key = fkey(sc[i]);
                if ((key & pmask) == prefix)
                    atomicAdd(&hist[(key >> sh) & 255], 1u);
            }
        }
        __syncthreads();
        if (t < 32) warp_select<8>(hist, kk, &s_idx2, &s_kk);
        __syncthreads();
        prefix |= s_idx2 << sh;
        pmask  |= 0xFFu << sh;
        kk = s_kk;
        __syncthreads();
    }
    const unsigned T = prefix;
    const int rem = kk;                               // ties at T still needed

    // ---- stage 3: classify ----
    if (!fb) {
        for (int i = t; i < cnt; i += 1024) {
            unsigned key = skey[i];
            if (key > T) {
                int p = atomicAdd(&s_cgt, 1);
                g_topk[b * Kk + p] = (int)sidx[i];
            } else if (key == T) {
                int e = atomicAdd(&s_eq, 1);
                if (e < rem) g_topk[b * Kk + (Kk - rem) + e] = (int)sidx[i];
            }
        }
    } else {
        const float* sc = (const float*)s4;
        for (int i = t; i < Nn; i += 1024) {
            unsigned key = fkey(sc[i]);
            if ((key >> 24) == selbin) {
                if (key > T) {
                    int p = atomicAdd(&s_cgt, 1);
                    g_topk[b * Kk + p] = i;
                } else if (key == T) {
                    int e = atomicAdd(&s_eq, 1);
                    if (e < rem) g_topk[b * Kk + (Kk - rem) + e] = i;
                }
            }
        }
    }
}

// ---------------- kernel 3: gather 8 channels/block + mean ------------------
__global__ void gather_kernel(const float* __restrict__ F,
                              float* __restrict__ out) {
    const int b  = blockIdx.y;
    const int c0 = blockIdx.x * 8;
    const int j  = threadIdx.x;                       // 256 == K

    const int idx = g_topk[b * Kk + j];
    const float* base = F + ((size_t)(b * Cn + c0)) * Nn + idx;

    float v[8];
#pragma unroll
    for (int u = 0; u < 8; u++) v[u] = __ldg(&base[(size_t)u * Nn]);

    __shared__ float red[8][8];
#pragma unroll
    for (int u = 0; u < 8; u++) {
        float s = v[u];
#pragma unroll
        for (int o = 16; o; o >>= 1) s += __shfl_down_sync(0xffffffffu, s, o);
        if ((j & 31) == 0) red[u][j >> 5] = s;
    }
    __syncthreads();
    if (j < 8) {
        float s = 0.f;
#pragma unroll
        for (int q = 0; q < 8; q++) s += red[j][q];
        out[b * Cn + c0 + j] = s * (1.0f / Kk);
    }
}

// ---------------- launcher ---------------------------------------------------
extern "C" void kernel_launch(void* const* d_in, const int* in_sizes, int n_in,
                              void* d_out, int out_size) {
    const float4* F  = (const float4*)d_in[0];
    const float*  w  = (const float*)d_in[1];
    float*        out = (float*)d_out;

    score_kernel  <<<Bn * NVEC / 256, 256>>>(F, w);
    selectk_kernel<<<Bn, 1024>>>();
    gather_kernel <<<dim3(Cn / 8, Bn), 256>>>((const float*)d_in[0], out);
}

// round 6
// speedup vs baseline: 1.0624x; 1.0624x over previous
#include <cuda_runtime.h>

#define Bn 4
#define Cn 256
#define Nn 131072          // D*H*W
#define NVEC2 (Nn / 2)     // 65536 float2 per batch (score kernel view)
#define NVEC4 (Nn / 4)     // 32768 float4 per batch (select kernel view)
#define Kk 256
#define FCAP 5632          // shared candidate capacity (expected ~2.9K)
#define GCAP 16384         // global candidate capacity per batch
#define SCTA 4             // select CTAs per batch

// ---------------- device scratch (static globals; no allocation) ------------
__device__ float2   g_scores2[Bn * NVEC2];  // 2 MiB scores
__device__ unsigned g_hist[Bn * 256];       // MSB-byte histograms (self-reset)
__device__ int      g_cgt[Bn];              // topk fill counters (self-reset)
__device__ int      g_ccand[Bn];            // candidate counters (self-reset)
__device__ int      g_arrive[Bn];           // CTA arrival counters (self-reset)
__device__ uint2    g_cand[Bn * GCAP];      // (key, idx) straddling-bin stash
__device__ int      g_topk[Bn * Kk];

// monotone float->uint key: larger float => larger key
__device__ __forceinline__ unsigned fkey(float f) {
    unsigned u = __float_as_uint(f);
    return (u & 0x80000000u) ? ~u : (u | 0x80000000u);
}

// Warp-parallel straddling-bin selection over 32*NPL bins (higher index =
// higher rank). Finds max bin i where count(bins > i) < kk <= count(bins >= i).
template<int NPL>
__device__ __forceinline__ void warp_select(const unsigned* __restrict__ h,
                                            int kk, unsigned* out_idx, int* out_kk) {
    const int lane = threadIdx.x & 31;
    unsigned loc[NPL];
    unsigned chunk = 0;
#pragma unroll
    for (int j = 0; j < NPL; j++) { loc[j] = h[lane * NPL + j]; chunk += loc[j]; }
    unsigned pref = chunk;                       // inclusive prefix low->high lane
#pragma unroll
    for (int o = 1; o < 32; o <<= 1) {
        unsigned v = __shfl_up_sync(0xffffffffu, pref, o);
        if (lane >= o) pref += v;
    }
    unsigned total = __shfl_sync(0xffffffffu, pref, 31);
    unsigned cum = total - pref;                 // entries in higher lanes
#pragma unroll
    for (int j = NPL - 1; j >= 0; j--) {
        unsigned nc = cum + loc[j];
        if (cum < (unsigned)kk && nc >= (unsigned)kk) {
            *out_idx = (unsigned)(lane * NPL + j);
            *out_kk  = kk - (int)cum;
        }
        cum = nc;
    }
}

// ---------------- kernel 1: score (float2/thread) + fused MSB histogram -----
__global__ void score_kernel(const float2* __restrict__ F,
                             const float*  __restrict__ w) {
    __shared__ float sw[Cn];
    __shared__ unsigned hist[256];
    for (int i = threadIdx.x; i < Cn; i += blockDim.x) sw[i] = w[i];
    for (int i = threadIdx.x; i < 256; i += blockDim.x) hist[i] = 0;
    __syncthreads();

    int v  = blockIdx.x * blockDim.x + threadIdx.x;   // [0, Bn*NVEC2)
    int b  = v >> 16;                                  // / NVEC2
    int nv = v & (NVEC2 - 1);
    const float2* base = F + (size_t)b * Cn * NVEC2 + nv;

    float ax = 0.f, ay = 0.f;
#pragma unroll 8
    for (int c = 0; c < Cn; c++) {
        float2 x = __ldcs(&base[(size_t)c * NVEC2]);  // streaming: no reuse
        float wc = sw[c];
        ax = fmaf(x.x, wc, ax);
        ay = fmaf(x.y, wc, ay);
    }
    g_scores2[v] = make_float2(ax, ay);

    unsigned kb[2] = { fkey(ax) >> 24, fkey(ay) >> 24 };
    const int lane = threadIdx.x & 31;
#pragma unroll
    for (int j = 0; j < 2; j++) {
        unsigned mask = __match_any_sync(0xffffffffu, kb[j]);
        if (lane == (__ffs(mask) - 1))
            atomicAdd(&hist[kb[j]], (unsigned)__popc(mask));
    }
    __syncthreads();
    unsigned* gh = g_hist + b * 256;
    for (int i = threadIdx.x; i < 256; i += blockDim.x)
        if (hist[i]) atomicAdd(&gh[i], hist[i]);
}

// ---------------- kernel 2: wide select (4 CTA/batch, last CTA refines) -----
__global__ void __launch_bounds__(1024, 1) selectk_kernel() {
    const int b   = blockIdx.x / SCTA;
    const int t   = threadIdx.x;
    const float4* s4 = (const float4*)g_scores2 + (size_t)b * NVEC4;

    __shared__ unsigned skey[FCAP];                   // 22 KB
    __shared__ unsigned sidx[FCAP];                   // 22 KB
    __shared__ unsigned hist[256];
    __shared__ unsigned s_selbin, s_idx2;
    __shared__ int s_kk, s_eq, s_last;

    // ---- stage 0: straddling MSB bin (all CTAs compute redundantly) ----
    if (t < 256) hist[t] = g_hist[b * 256 + t];
    __syncthreads();
    if (t < 32) warp_select<8>(hist, Kk, &s_selbin, &s_kk);
    __syncthreads();
    const unsigned selbin = s_selbin;
    int kk = s_kk;

    // ---- stage 1: scan my quarter, direct-write winners + stash cands ----
    const int q  = blockIdx.x % SCTA;
    const int i0 = q * (NVEC4 / SCTA), i1 = i0 + NVEC4 / SCTA;
    for (int i = i0 + t; i < i1; i += 1024) {
        float4 s = s4[i];
        float sv[4] = { s.x, s.y, s.z, s.w };
#pragma unroll
        for (int j = 0; j < 4; j++) {
            unsigned key = fkey(sv[j]);
            unsigned bin = key >> 24;
            if (bin < selbin) continue;
            int n = i * 4 + j;
            if (bin > selbin) {
                int p = atomicAdd(&g_cgt[b], 1);      // guaranteed < Kk
                g_topk[b * Kk + p] = n;
            } else {
                int p = atomicAdd(&g_ccand[b], 1);
                if (p < GCAP) g_cand[b * GCAP + p] = make_uint2(key, (unsigned)n);
            }
        }
    }

    // ---- elect last CTA of this batch ----
    __threadfence();
    __syncthreads();
    if (t == 0) s_last = (atomicAdd(&g_arrive[b], 1) == SCTA - 1);
    __syncthreads();
    if (!s_last) return;

    // ---- stage 2 (last CTA): radix refine candidates ----
    const int cnt_raw = g_ccand[b];
    const int cnt = cnt_raw < GCAP ? cnt_raw : GCAP;
    const bool fb = (cnt_raw > GCAP);
    const uint2* cand = g_cand + b * GCAP;
    const float* sc = (const float*)s4;

    if (!fb) {                                        // pull to shared (<= FCAP path)
        for (int i = t; i < cnt && i < FCAP; i += 1024) {
            uint2 c = cand[i];
            skey[i] = c.x; sidx[i] = c.y;
        }
    }
    __syncthreads();
    const bool inshared = !fb && (cnt <= FCAP);

    unsigned prefix = selbin << 24, pmask = 0xFF000000u;
    for (int level = 2; level >= 0; level--) {
        if (t < 256) hist[t] = 0;
        __syncthreads();
        const int sh = 8 * level;
        if (inshared) {
            for (int i = t; i < cnt; i += 1024) {
                unsigned key = skey[i];
                if ((key & pmask) == prefix)
                    atomicAdd(&hist[(key >> sh) & 255], 1u);
            }
        } else if (!fb) {
            for (int i = t; i < cnt; i += 1024) {
                unsigned key = cand[i].x;
                if ((key & pmask) == prefix)
                    atomicAdd(&hist[(key >> sh) & 255], 1u);
            }
        } else {
            for (int i = t; i < Nn; i += 1024) {
                unsigned key = fkey(sc[i]);
                if ((key & pmask) == prefix)
                    atomicAdd(&hist[(key >> sh) & 255], 1u);
            }
        }
        __syncthreads();
        if (t < 32) warp_select<8>(hist, kk, &s_idx2, &s_kk);
        __syncthreads();
        prefix |= s_idx2 << sh;
        pmask  |= 0xFFu << sh;
        kk = s_kk;
        __syncthreads();
    }
    const unsigned T = prefix;
    const int rem = kk;                               // ties at T still needed
    if (t == 0) s_eq = 0;
    __syncthreads();

    // ---- stage 3: classify ----
    if (inshared) {
        for (int i = t; i < cnt; i += 1024) {
            unsigned key = skey[i];
            if (key > T) {
                int p = atomicAdd(&g_cgt[b], 1);
                g_topk[b * Kk + p] = (int)sidx[i];
            } else if (key == T) {
                int e = atomicAdd(&s_eq, 1);
                if (e < rem) g_topk[b * Kk + (Kk - rem) + e] = (int)sidx[i];
            }
        }
    } else if (!fb) {
        for (int i = t; i < cnt; i += 1024) {
            uint2 c = cand[i];
            if (c.x > T) {
                int p = atomicAdd(&g_cgt[b], 1);
                g_topk[b * Kk + p] = (int)c.y;
            } else if (c.x == T) {
                int e = atomicAdd(&s_eq, 1);
                if (e < rem) g_topk[b * Kk + (Kk - rem) + e] = (int)c.y;
            }
        }
    } else {
        for (int i = t; i < Nn; i += 1024) {
            unsigned key = fkey(sc[i]);
            if ((key >> 24) == selbin) {
                if (key > T) {
                    int p = atomicAdd(&g_cgt[b], 1);
                    g_topk[b * Kk + p] = i;
                } else if (key == T) {
                    int e = atomicAdd(&s_eq, 1);
                    if (e < rem) g_topk[b * Kk + (Kk - rem) + e] = i;
                }
            }
        }
    }

    // ---- epilogue: reset per-batch state for next graph replay ----
    __syncthreads();
    if (t < 256) g_hist[b * 256 + t] = 0;
    if (t == 0) { g_cgt[b] = 0; g_ccand[b] = 0; g_arrive[b] = 0; }
}

// ---------------- kernel 3: gather 8 channels/block + mean ------------------
__global__ void gather_kernel(const float* __restrict__ F,
                              float* __restrict__ out) {
    const int b  = blockIdx.y;
    const int c0 = blockIdx.x * 8;
    const int j  = threadIdx.x;                       // 256 == K

    const int idx = g_topk[b * Kk + j];
    const float* base = F + ((size_t)(b * Cn + c0)) * Nn + idx;

    float v[8];
#pragma unroll
    for (int u = 0; u < 8; u++) v[u] = __ldg(&base[(size_t)u * Nn]);

    __shared__ float red[8][8];
#pragma unroll
    for (int u = 0; u < 8; u++) {
        float s = v[u];
#pragma unroll
        for (int o = 16; o; o >>= 1) s += __shfl_down_sync(0xffffffffu, s, o);
        if ((j & 31) == 0) red[u][j >> 5] = s;
    }
    __syncthreads();
    if (j < 8) {
        float s = 0.f;
#pragma unroll
        for (int q = 0; q < 8; q++) s += red[j][q];
        out[b * Cn + c0 + j] = s * (1.0f / Kk);
    }
}

// ---------------- launcher ---------------------------------------------------
extern "C" void kernel_launch(void* const* d_in, const int* in_sizes, int n_in,
                              void* d_out, int out_size) {
    const float2* F  = (const float2*)d_in[0];
    const float*  w  = (const float*)d_in[1];
    float*        out = (float*)d_out;

    score_kernel  <<<Bn * NVEC2 / 256, 256>>>(F, w);
    selectk_kernel<<<Bn * SCTA, 1024>>>();
    gather_kernel <<<dim3(Cn / 8, Bn), 256>>>((const float*)d_in[0], out);
}

// round 7
// speedup vs baseline: 1.1298x; 1.0635x over previous
#include <cuda_runtime.h>

#define Bn 4
#define Cn 256
#define Nn 131072          // D*H*W
#define NVEC2 (Nn / 2)     // 65536 float2 per batch (score view)
#define NVEC4 (Nn / 4)     // 32768 float4 per batch (select view)
#define Kk 256
#define FCAP 5632          // shared candidate capacity (expected ~2.9K)
#define GCAP 16384         // global candidate capacity per batch
#define SCTA 32            // select/gather CTAs per batch (grid = 128 <= 148)

// ---------------- device scratch (static globals; no allocation) ------------
__device__ float2   g_scores2[Bn * NVEC2];  // 2 MiB scores
__device__ unsigned g_hist[Bn * 256];       // MSB-byte histograms (self-reset)
__device__ int      g_cgt[Bn];              // topk fill counters (self-reset)
__device__ int      g_ccand[Bn];            // candidate counters (self-reset)
__device__ int      g_arrive[Bn];           // scan arrival counters (self-reset)
__device__ int      g_arr2[Bn];             // post-spin counters (self-reset)
__device__ int      g_done[Bn];             // refine-done flags (self-reset)
__device__ uint2    g_cand[Bn * GCAP];      // (key, idx) straddling-bin stash
__device__ int      g_topk[Bn * Kk];

// monotone float->uint key: larger float => larger key
__device__ __forceinline__ unsigned fkey(float f) {
    unsigned u = __float_as_uint(f);
    return (u & 0x80000000u) ? ~u : (u | 0x80000000u);
}

// Warp-parallel straddling-bin selection over 32*NPL bins (higher index =
// higher rank). Finds max bin i where count(bins > i) < kk <= count(bins >= i).
template<int NPL>
__device__ __forceinline__ void warp_select(const unsigned* __restrict__ h,
                                            int kk, unsigned* out_idx, int* out_kk) {
    const int lane = threadIdx.x & 31;
    unsigned loc[NPL];
    unsigned chunk = 0;
#pragma unroll
    for (int j = 0; j < NPL; j++) { loc[j] = h[lane * NPL + j]; chunk += loc[j]; }
    unsigned pref = chunk;                       // inclusive prefix low->high lane
#pragma unroll
    for (int o = 1; o < 32; o <<= 1) {
        unsigned v = __shfl_up_sync(0xffffffffu, pref, o);
        if (lane >= o) pref += v;
    }
    unsigned total = __shfl_sync(0xffffffffu, pref, 31);
    unsigned cum = total - pref;                 // entries in higher lanes
#pragma unroll
    for (int j = NPL - 1; j >= 0; j--) {
        unsigned nc = cum + loc[j];
        if (cum < (unsigned)kk && nc >= (unsigned)kk) {
            *out_idx = (unsigned)(lane * NPL + j);
            *out_kk  = kk - (int)cum;
        }
        cum = nc;
    }
}

// ---------------- kernel 1: score (float2/thread) + fused MSB histogram -----
__global__ void score_kernel(const float2* __restrict__ F,
                             const float*  __restrict__ w) {
    __shared__ float sw[Cn];
    __shared__ unsigned hist[256];
    for (int i = threadIdx.x; i < Cn; i += blockDim.x) sw[i] = w[i];
    for (int i = threadIdx.x; i < 256; i += blockDim.x) hist[i] = 0;
    __syncthreads();

    int v  = blockIdx.x * blockDim.x + threadIdx.x;   // [0, Bn*NVEC2)
    int b  = v >> 16;                                  // / NVEC2
    int nv = v & (NVEC2 - 1);
    const float2* base = F + (size_t)b * Cn * NVEC2 + nv;

    float ax = 0.f, ay = 0.f;
#pragma unroll 8
    for (int c = 0; c < Cn; c++) {
        float2 x = __ldcs(&base[(size_t)c * NVEC2]);  // streaming: no reuse
        float wc = sw[c];
        ax = fmaf(x.x, wc, ax);
        ay = fmaf(x.y, wc, ay);
    }
    g_scores2[v] = make_float2(ax, ay);

    unsigned kb[2] = { fkey(ax) >> 24, fkey(ay) >> 24 };
    const int lane = threadIdx.x & 31;
#pragma unroll
    for (int j = 0; j < 2; j++) {
        unsigned mask = __match_any_sync(0xffffffffu, kb[j]);
        if (lane == (__ffs(mask) - 1))
            atomicAdd(&hist[kb[j]], (unsigned)__popc(mask));
    }
    __syncthreads();
    unsigned* gh = g_hist + b * 256;
    for (int i = threadIdx.x; i < 256; i += blockDim.x)
        if (hist[i]) atomicAdd(&gh[i], hist[i]);
}

// ---------------- kernel 2: fused select + gather (persistent, 128 CTAs) ----
__global__ void __launch_bounds__(1024, 1) select_gather_kernel(
        const float* __restrict__ F, float* __restrict__ out) {
    const int blk = blockIdx.x;
    const int b   = blk >> 5;          // batch
    const int g   = blk & 31;          // group within batch
    const int t   = threadIdx.x;
    const float4* s4 = (const float4*)g_scores2 + (size_t)b * NVEC4;

    __shared__ unsigned skey[FCAP];    // 22 KB
    __shared__ unsigned sidx[FCAP];    // 22 KB
    __shared__ unsigned hist[256];
    __shared__ unsigned s_selbin, s_idx2;
    __shared__ int s_kk, s_eq;

    // ---- stage 0: straddling MSB bin (all CTAs compute redundantly) ----
    if (t < 256) hist[t] = g_hist[b * 256 + t];
    __syncthreads();
    if (t < 32) warp_select<8>(hist, Kk, &s_selbin, &s_kk);
    __syncthreads();
    const unsigned selbin = s_selbin;
    int kk = s_kk;

    // ---- stage 1: scan my slice (1 float4/thread) ----
    {
        const int i = g * (NVEC4 / SCTA) + t;
        float4 s = s4[i];
        float sv[4] = { s.x, s.y, s.z, s.w };
#pragma unroll
        for (int j = 0; j < 4; j++) {
            unsigned key = fkey(sv[j]);
            unsigned bin = key >> 24;
            if (bin < selbin) continue;
            int n = i * 4 + j;
            if (bin > selbin) {
                int p = atomicAdd(&g_cgt[b], 1);      // guaranteed < Kk
                g_topk[b * Kk + p] = n;
            } else {
                int p = atomicAdd(&g_ccand[b], 1);
                if (p < GCAP) g_cand[b * GCAP + p] = make_uint2(key, (unsigned)n);
            }
        }
    }
    __threadfence();
    __syncthreads();
    if (t == 0) atomicAdd(&g_arrive[b], 1);

    if (g == 0) {
        // ================= leader: refine threshold & finalize topk ==========
        if (t == 0) {
            unsigned ns = 8;
            while (((volatile int*)g_arrive)[b] != SCTA) {
                __nanosleep(ns); if (ns < 256) ns <<= 1;
            }
        }
        __syncthreads();
        __threadfence();

        const int cnt_raw = g_ccand[b];
        const int cnt = cnt_raw < GCAP ? cnt_raw : GCAP;
        const bool fb = (cnt_raw > GCAP);
        const uint2* cand = g_cand + b * GCAP;
        const float* sc = (const float*)s4;

        if (!fb) {
            for (int i = t; i < cnt && i < FCAP; i += 1024) {
                uint2 c = cand[i];
                skey[i] = c.x; sidx[i] = c.y;
            }
        }
        __syncthreads();
        const bool inshared = !fb && (cnt <= FCAP);

        unsigned prefix = selbin << 24, pmask = 0xFF000000u;
        for (int level = 2; level >= 0; level--) {
            if (t < 256) hist[t] = 0;
            __syncthreads();
            const int sh = 8 * level;
            if (inshared) {
                for (int i = t; i < cnt; i += 1024) {
                    unsigned key = skey[i];
                    if ((key & pmask) == prefix)
                        atomicAdd(&hist[(key >> sh) & 255], 1u);
                }
            } else if (!fb) {
                for (int i = t; i < cnt; i += 1024) {
                    unsigned key = cand[i].x;
                    if ((key & pmask) == prefix)
                        atomicAdd(&hist[(key >> sh) & 255], 1u);
                }
            } else {
                for (int i = t; i < Nn; i += 1024) {
                    unsigned key = fkey(sc[i]);
                    if ((key & pmask) == prefix)
                        atomicAdd(&hist[(key >> sh) & 255], 1u);
                }
            }
            __syncthreads();
            if (t < 32) warp_select<8>(hist, kk, &s_idx2, &s_kk);
            __syncthreads();
            prefix |= s_idx2 << sh;
            pmask  |= 0xFFu << sh;
            kk = s_kk;
            __syncthreads();
        }
        const unsigned T = prefix;
        const int rem = kk;
        if (t == 0) s_eq = 0;
        __syncthreads();

        if (inshared) {
            for (int i = t; i < cnt; i += 1024) {
                unsigned key = skey[i];
                if (key > T) {
                    int p = atomicAdd(&g_cgt[b], 1);
                    g_topk[b * Kk + p] = (int)sidx[i];
                } else if (key == T) {
                    int e = atomicAdd(&s_eq, 1);
                    if (e < rem) g_topk[b * Kk + (Kk - rem) + e] = (int)sidx[i];
                }
            }
        } else if (!fb) {
            for (int i = t; i < cnt; i += 1024) {
                uint2 c = cand[i];
                if (c.x > T) {
                    int p = atomicAdd(&g_cgt[b], 1);
                    g_topk[b * Kk + p] = (int)c.y;
                } else if (c.x == T) {
                    int e = atomicAdd(&s_eq, 1);
                    if (e < rem) g_topk[b * Kk + (Kk - rem) + e] = (int)c.y;
                }
            }
        } else {
            for (int i = t; i < Nn; i += 1024) {
                unsigned key = fkey(sc[i]);
                if ((key >> 24) == selbin) {
                    if (key > T) {
                        int p = atomicAdd(&g_cgt[b], 1);
                        g_topk[b * Kk + p] = i;
                    } else if (key == T) {
                        int e = atomicAdd(&s_eq, 1);
                        if (e < rem) g_topk[b * Kk + (Kk - rem) + e] = i;
                    }
                }
            }
        }
        __syncthreads();

        // reset per-batch state for next graph replay, then signal done
        if (t < 256) g_hist[b * 256 + t] = 0;
        if (t == 0) { g_cgt[b] = 0; g_ccand[b] = 0; g_arrive[b] = 0; }
        __syncthreads();
        __threadfence();
        if (t == 0) atomicExch(&g_done[b], 1);
    } else {
        // ================= peers: wait for leader ============================
        if (t == 0) {
            unsigned ns = 8;
            while (((volatile int*)g_done)[b] == 0) {
                __nanosleep(ns); if (ns < 256) ns <<= 1;
            }
        }
        __syncthreads();
        __threadfence();
    }

    // last CTA through the gate resets the done flag for the next replay
    if (t == 0) {
        if (atomicAdd(&g_arr2[b], 1) == SCTA - 1) {
            g_arr2[b] = 0;
            g_done[b] = 0;
        }
    }

    // ---- phase B: gather 8 channels for this (b, g) + mean ----
    const int c0 = g * 8;
    const int j  = t & 255;            // voxel slot
    const int cp = t >> 8;             // 0..3 channel pair selector
    const int idx = g_topk[b * Kk + j];
    const float* fb2 = F + ((size_t)(b * Cn + c0 + cp)) * Nn + idx;
    float v0 = __ldg(fb2);
    float v1 = __ldg(fb2 + 4 * (size_t)Nn);

#pragma unroll
    for (int o = 16; o; o >>= 1) {
        v0 += __shfl_down_sync(0xffffffffu, v0, o);
        v1 += __shfl_down_sync(0xffffffffu, v1, o);
    }
    __shared__ float red[8][8];
    const int wg = (t >> 5) & 7;       // warp index within 256-thread group
    if ((t & 31) == 0) { red[cp][wg] = v0; red[cp + 4][wg] = v1; }
    __syncthreads();
    if (t < 8) {
        float s = 0.f;
#pragma unroll
        for (int q = 0; q < 8; q++) s += red[t][q];
        out[b * Cn + c0 + t] = s * (1.0f / Kk);
    }
}

// ---------------- launcher ---------------------------------------------------
extern "C" void kernel_launch(void* const* d_in, const int* in_sizes, int n_in,
                              void* d_out, int out_size) {
    const float2* F  = (const float2*)d_in[0];
    const float*  w  = (const float*)d_in[1];
    float*        out = (float*)d_out;

    score_kernel<<<Bn * NVEC2 / 256, 256>>>(F, w);
    select_gather_kernel<<<Bn * SCTA, 1024>>>((const float*)d_in[0], out);
}

// round 9
// speedup vs baseline: 1.1512x; 1.0189x over previous
#include <cuda_runtime.h>

#define Bn 4
#define Cn 256
#define Nn 131072           // D*H*W
#define NVEC2 (Nn / 2)      // 65536 float2 per batch
#define NVEC4 (Nn / 4)      // 32768 float4 per batch
#define Kk 256
#define GCAP 16384          // global candidate capacity per batch
#define CPB 64              // CTAs per batch (grid = 4*64 = 256)

// ---------------- device scratch (static globals; no allocation) ------------
__device__ float4   g_scores4[Bn * NVEC4];  // 2 MiB scores (16B-aligned)
__device__ unsigned g_hist[Bn * 256];       // MSB-byte histograms (self-reset)
__device__ int      g_cgt[Bn];              // topk fill counters (self-reset)
__device__ int      g_ccand[Bn];            // candidate counters (self-reset)
__device__ int      g_barA[Bn];             // score->select barrier (self-reset)
__device__ int      g_barB[Bn];             // scan->refine barrier (self-reset)
__device__ int      g_done[Bn];             // refine-done flags (self-reset)
__device__ int      g_arr2[Bn];             // done-gate counters (self-reset)
__device__ uint2    g_cand[Bn * GCAP];      // (key, idx) straddling-bin stash
__device__ int      g_topk[Bn * Kk];

// monotone float->uint key: larger float => larger key
__device__ __forceinline__ unsigned fkey(float f) {
    unsigned u = __float_as_uint(f);
    return (u & 0x80000000u) ? ~u : (u | 0x80000000u);
}

// Warp-parallel straddling-bin selection over 32*NPL bins (higher index =
// higher rank). Finds max bin i where count(bins > i) < kk <= count(bins >= i).
template<int NPL>
__device__ __forceinline__ void warp_select(const unsigned* __restrict__ h,
                                            int kk, unsigned* out_idx, int* out_kk) {
    const int lane = threadIdx.x & 31;
    unsigned loc[NPL];
    unsigned chunk = 0;
#pragma unroll
    for (int j = 0; j < NPL; j++) { loc[j] = h[lane * NPL + j]; chunk += loc[j]; }
    unsigned pref = chunk;                       // inclusive prefix low->high lane
#pragma unroll
    for (int o = 1; o < 32; o <<= 1) {
        unsigned v = __shfl_up_sync(0xffffffffu, pref, o);
        if (lane >= o) pref += v;
    }
    unsigned total = __shfl_sync(0xffffffffu, pref, 31);
    unsigned cum = total - pref;                 // entries in higher lanes
#pragma unroll
    for (int j = NPL - 1; j >= 0; j--) {
        unsigned nc = cum + loc[j];
        if (cum < (unsigned)kk && nc >= (unsigned)kk) {
            *out_idx = (unsigned)(lane * NPL + j);
            *out_kk  = kk - (int)cum;
        }
        cum = nc;
    }
}

__device__ __forceinline__ void spin_until(volatile int* p, int target) {
    unsigned ns = 8;
    while (*p < target) { __nanosleep(ns); if (ns < 256) ns <<= 1; }
}

// ================= one persistent kernel: score+select+gather ================
__global__ void __launch_bounds__(1024, 2) fused_kernel(
        const float2* __restrict__ F2, const float* __restrict__ Ff,
        const float*  __restrict__ w,  float* __restrict__ out) {
    const int blk = blockIdx.x;
    const int b   = blk >> 6;            // batch (64 CTAs each)
    const int g   = blk & 63;            // CTA within batch
    const int t   = threadIdx.x;

    __shared__ float sw[Cn];
    __shared__ unsigned hist[256];
    __shared__ unsigned s_selbin, s_idx2;
    __shared__ int s_kk, s_eq;

    // ---------------- phase 1: score my 1024-float2 slice -------------------
    for (int i = t; i < Cn; i += 1024) sw[i] = w[i];
    if (t < 256) hist[t] = 0;
    __syncthreads();

    {
        const int nv = g * 1024 + t;                 // [0, NVEC2)
        const float2* base = F2 + (size_t)b * Cn * NVEC2 + nv;
        float ax = 0.f, ay = 0.f;
#pragma unroll 8
        for (int c = 0; c < Cn; c++) {
            float2 x = __ldcs(&base[(size_t)c * NVEC2]);
            float wc = sw[c];
            ax = fmaf(x.x, wc, ax);
            ay = fmaf(x.y, wc, ay);
        }
        ((float2*)g_scores4)[b * NVEC2 + nv] = make_float2(ax, ay);

        unsigned kb[2] = { fkey(ax) >> 24, fkey(ay) >> 24 };
        const int lane = t & 31;
#pragma unroll
        for (int j = 0; j < 2; j++) {
            unsigned mask = __match_any_sync(0xffffffffu, kb[j]);
            if (lane == (__ffs(mask) - 1))
                atomicAdd(&hist[kb[j]], (unsigned)__popc(mask));
        }
    }
    __syncthreads();
    if (t < 256 && hist[t]) atomicAdd(&g_hist[b * 256 + t], hist[t]);

    // ---------------- barrier A: my batch's 64 CTAs done scoring ------------
    __threadfence();
    __syncthreads();
    if (t == 0) {
        atomicAdd(&g_barA[b], 1);
        spin_until(&g_barA[b], CPB);
    }
    __syncthreads();
    __threadfence();

    // ---------------- phase 2: select ---------------------------------------
    if (t < 256) hist[t] = g_hist[b * 256 + t];
    __syncthreads();
    if (t < 32) warp_select<8>(hist, Kk, &s_selbin, &s_kk);
    __syncthreads();
    const unsigned selbin = s_selbin;
    int kk = s_kk;

    const float4* s4 = g_scores4 + (size_t)b * NVEC4;
    if (t < 512) {
        const int i = g * 512 + t;                   // [0, NVEC4)
        float4 s = s4[i];
        float sv[4] = { s.x, s.y, s.z, s.w };
#pragma unroll
        for (int j = 0; j < 4; j++) {
            unsigned key = fkey(sv[j]);
            unsigned bin = key >> 24;
            if (bin < selbin) continue;
            int n = i * 4 + j;
            if (bin > selbin) {
                int p = atomicAdd(&g_cgt[b], 1);     // guaranteed < Kk
                g_topk[b * Kk + p] = n;
            } else {
                int p = atomicAdd(&g_ccand[b], 1);
                if (p < GCAP) g_cand[b * GCAP + p] = make_uint2(key, (unsigned)n);
            }
        }
    }
    __threadfence();
    __syncthreads();
    if (t == 0) atomicAdd(&g_barB[b], 1);

    if (g == 0) {
        // ===== leader: refine threshold & finalize topk =====
        if (t == 0) spin_until(&g_barB[b], CPB);
        __syncthreads();
        __threadfence();

        const int cnt_raw = g_ccand[b];
        const int cnt = cnt_raw < GCAP ? cnt_raw : GCAP;
        const bool fb = (cnt_raw > GCAP);
        const uint2* cand = g_cand + b * GCAP;
        const float* sc = (const float*)s4;

        unsigned prefix = selbin << 24, pmask = 0xFF000000u;
        for (int level = 2; level >= 0; level--) {
            if (t < 256) hist[t] = 0;
            __syncthreads();
            const int sh = 8 * level;
            if (!fb) {
                for (int i = t; i < cnt; i += 1024) {
                    unsigned key = cand[i].x;
                    if ((key & pmask) == prefix)
                        atomicAdd(&hist[(key >> sh) & 255], 1u);
                }
            } else {
                for (int i = t; i < Nn; i += 1024) {
                    unsigned key = fkey(sc[i]);
                    if ((key & pmask) == prefix)
                        atomicAdd(&hist[(key >> sh) & 255], 1u);
                }
            }
            __syncthreads();
            if (t < 32) warp_select<8>(hist, kk, &s_idx2, &s_kk);
            __syncthreads();
            prefix |= s_idx2 << sh;
            pmask  |= 0xFFu << sh;
            kk = s_kk;
            __syncthreads();
        }
        const unsigned T = prefix;
        const int rem = kk;
        if (t == 0) s_eq = 0;
        __syncthreads();

        if (!fb) {
            for (int i = t; i < cnt; i += 1024) {
                uint2 c = cand[i];
                if (c.x > T) {
                    int p = atomicAdd(&g_cgt[b], 1);
                    g_topk[b * Kk + p] = (int)c.y;
                } else if (c.x == T) {
                    int e = atomicAdd(&s_eq, 1);
                    if (e < rem) g_topk[b * Kk + (Kk - rem) + e] = (int)c.y;
                }
            }
        } else {
            for (int i = t; i < Nn; i += 1024) {
                unsigned key = fkey(sc[i]);
                if ((key >> 24) == selbin) {
                    if (key > T) {
                        int p = atomicAdd(&g_cgt[b], 1);
                        g_topk[b * Kk + p] = i;
                    } else if (key == T) {
                        int e = atomicAdd(&s_eq, 1);
                        if (e < rem) g_topk[b * Kk + (Kk - rem) + e] = i;
                    }
                }
            }
        }
        __syncthreads();

        // reset per-batch state for next graph replay (all 64 passed A and B)
        if (t < 256) g_hist[b * 256 + t] = 0;
        if (t == 0) { g_cgt[b] = 0; g_ccand[b] = 0; g_barA[b] = 0; g_barB[b] = 0; }
        __syncthreads();
        __threadfence();
        if (t == 0) atomicExch(&g_done[b], 1);
    } else {
        // ===== peers: wait for leader =====
        if (t == 0) spin_until(&g_done[b], 1);
        __syncthreads();
        __threadfence();
    }

    // last CTA through the gate resets the done flag for the next replay
    if (t == 0) {
        if (atomicAdd(&g_arr2[b], 1) == CPB - 1) {
            g_arr2[b] = 0;
            g_done[b] = 0;
        }
    }

    // ---------------- phase 3: gather 4 channels for this CTA + mean --------
    const int c0 = g * 4;                // 64 CTAs x 4 channels = 256
    const int j  = t & 255;              // voxel slot
    const int cp = t >> 8;               // 0..3 channel selector
    const int idx = g_topk[b * Kk + j];
    float v = __ldg(Ff + ((size_t)(b * Cn + c0 + cp)) * Nn + idx);

#pragma unroll
    for (int o = 16; o; o >>= 1) v += __shfl_down_sync(0xffffffffu, v, o);

    __shared__ float red[4][8];
    const int wg = (t >> 5) & 7;         // warp index within 256-thread group
    if ((t & 31) == 0) red[cp][wg] = v;
    __syncthreads();
    if (t < 4) {
        float s = 0.f;
#pragma unroll
        for (int q = 0; q < 8; q++) s += red[t][q];
        out[b * Cn + c0 + t] = s * (1.0f / Kk);
    }
}

// ---------------- launcher: single persistent kernel -------------------------
extern "C" void kernel_launch(void* const* d_in, const int* in_sizes, int n_in,
                              void* d_out, int out_size) {
    const float2* F2 = (const float2*)d_in[0];
    const float*  Ff = (const float*)d_in[0];
    const float*  w  = (const float*)d_in[1];
    float*        out = (float*)d_out;

    fused_kernel<<<Bn * CPB, 1024>>>(F2, Ff, w, out);
}